// round 15
// baseline (speedup 1.0000x reference)
#include <cuda_runtime.h>
#include <cuda_fp16.h>
#include <cstdint>

#define THREADS 128
#define NPTS 128
#define PI_F 3.14159265358979323846f

// ---------------- pre-formatted weight scratch (B-fragment order, fp16) -------
// hidden l(0..6): base l*57344, chunk c: +c*14336
//   j-block (1024B): half h=nb>>1 at h*512, lane*16 holds frags (2h),(2h+1) 8B each
// layer0: base G_L0, chunk stride 6144, same j-block layout (j 0..5)
// final : base G_FIN, frag j*256 + lane*8 (single n-block, n>=4 zero)
#define L_STRIDE   57344u
#define C_STRIDE   14336u
#define G_L0       401408u
#define L0_CSTRIDE 6144u
#define G_FIN      425984u
#define G_TOT      429568u
__device__ __align__(16) unsigned char g_wt[G_TOT];

// ---------------- smem (bytes) -------------------------------------------------
#define OFF_RING 0u          // 2 x 14336 weight chunk ring
#define OFF_T    28672u      // lane-private activation stash: 8 wt x 8 j x 512
#define OFF_ENC  61440u      // enc frags ej=3..5 in smem: 8 wt x 3 x 512
#define SMEM_TOT 73728u

// ---------------- helpers ------------------------------------------------------
__device__ __forceinline__ void mma_f16(float* d, const uint32_t* a, uint32_t b0, uint32_t b1){
    asm("mma.sync.aligned.m16n8k16.row.col.f32.f16.f16.f32 "
        "{%0,%1,%2,%3},{%4,%5,%6,%7},{%8,%9},{%0,%1,%2,%3};"
        : "+f"(d[0]), "+f"(d[1]), "+f"(d[2]), "+f"(d[3])
        : "r"(a[0]), "r"(a[1]), "r"(a[2]), "r"(a[3]), "r"(b0), "r"(b1));
}
__device__ __forceinline__ void cp16(uint32_t s, const void* g){
    asm volatile("cp.async.cg.shared.global [%0], [%1], 16;" :: "r"(s), "l"(g));
}
__device__ __forceinline__ uint32_t packh(float v0, float v1){
    __half2 hp = __halves2half2(__float2half_rn(v0), __float2half_rn(v1));
    return *(uint32_t*)&hp;
}

// ---------------- prep: fp32 weights -> fp16 B-fragment order ------------------
__global__ void prep_kernel(const float* __restrict__ W0, const float* __restrict__ Wh,
                            const float* __restrict__ Wl){
    int i = blockIdx.x * blockDim.x + threadIdx.x;
    const int NH = 7 * 28672, NL0 = 96 * 128, NF = 224 * 8;
    if (i >= NH + NL0 + NF) return;
    float v; uint32_t addr; int k, n;
    if (i < NH){
        int l = i / 28672, r = i % 28672; k = r / 128; n = r % 128;
        v = Wh[(l * 224 + k) * 128 + n];
        int nb = (n >> 3) & 3;
        uint32_t lanei = (uint32_t)((n & 7) * 4 + ((k & 7) >> 1));
        addr = (uint32_t)l * L_STRIDE + (uint32_t)(n >> 5) * C_STRIDE
             + (uint32_t)(k >> 4) * 1024u + (uint32_t)(nb >> 1) * 512u
             + lanei * 16u + (uint32_t)(nb & 1) * 8u
             + (uint32_t)((k >> 3) & 1) * 4u + (uint32_t)(k & 1) * 2u;
    } else if (i < NH + NL0){
        int q = i - NH; k = q / 128; n = q % 128;
        v = W0[k * 128 + n];
        int nb = (n >> 3) & 3;
        uint32_t lanei = (uint32_t)((n & 7) * 4 + ((k & 7) >> 1));
        addr = G_L0 + (uint32_t)(n >> 5) * L0_CSTRIDE
             + (uint32_t)(k >> 4) * 1024u + (uint32_t)(nb >> 1) * 512u
             + lanei * 16u + (uint32_t)(nb & 1) * 8u
             + (uint32_t)((k >> 3) & 1) * 4u + (uint32_t)(k & 1) * 2u;
    } else {
        int q = i - NH - NL0; k = q / 8; n = q % 8;
        v = (n < 4) ? Wl[k * 4 + n] : 0.0f;
        uint32_t lanei = (uint32_t)((n & 7) * 4 + ((k & 7) >> 1));
        addr = G_FIN + (uint32_t)(k >> 4) * 256u + lanei * 8u
             + (uint32_t)((k >> 3) & 1) * 4u + (uint32_t)(k & 1) * 2u;
    }
    *(__half*)(g_wt + addr) = __float2half_rn(v);
}

// ---------------- main fused kernel --------------------------------------------
__global__ void __launch_bounds__(THREADS, 3)
nf_main(const float* __restrict__ qp, const float* __restrict__ b0g,
        const float* __restrict__ bhg, const float* __restrict__ blg,
        float* __restrict__ out)
{
    extern __shared__ char smc[];
    const int tid = threadIdx.x, w = tid >> 5, lane = tid & 31;
    const int l4 = lane >> 2, lm = lane & 3;
    const int gp0 = blockIdx.x * NPTS;
    const uint32_t sb = (uint32_t)__cvta_generic_to_shared(smc);

    // issue loads for global chunk pc into slot pc&1 (one commit group per chunk)
    auto issue_load = [&](int pc){
        if (pc > 32) return;
        const unsigned char* src; uint32_t bytes;
        if (pc < 4)      { src = g_wt + G_L0 + (uint32_t)pc * L0_CSTRIDE; bytes = L0_CSTRIDE; }
        else if (pc < 32){ int q = pc - 4;
                           src = g_wt + (uint32_t)(q >> 2) * L_STRIDE + (uint32_t)(q & 3) * C_STRIDE;
                           bytes = C_STRIDE; }
        else             { src = g_wt + G_FIN; bytes = 3584u; }
        uint32_t dst = sb + OFF_RING + (uint32_t)(pc & 1) * C_STRIDE;
        for (uint32_t i = (uint32_t)tid * 16u; i < bytes; i += THREADS * 16u)
            cp16(dst + i, src + i);
        asm volatile("cp.async.commit_group;");
    };
    // single barrier per chunk: load(c) visible; slot of c-1 provably free for c+1
    auto chunk_gate = [&](int cid){
        asm volatile("cp.async.wait_group 0;");
        __syncthreads();
        issue_load(cid + 1);
    };

    // kick off first chunk, then encoding overlaps the load
    issue_load(0);

    uint32_t A[2][8][4];      // activation A-frags (2 M-tiles x 8 j)
    uint32_t Ereg[2][3][4];   // enc frags ej=0..2 in registers

    // ---- NeRF encoding into A-fragment order (fp16, 2 M-tiles) ----
    {
        float xa[2][2][3];
        #pragma unroll
        for (int t = 0; t < 2; t++)
            #pragma unroll
            for (int r = 0; r < 2; r++)
                #pragma unroll
                for (int c = 0; c < 3; c++)
                    xa[t][r][c] = __ldg(qp + (gp0 + w * 32 + t * 16 + l4 + r * 8) * 3 + c);
        #pragma unroll
        for (int t = 0; t < 2; t++){
            #pragma unroll
            for (int j = 0; j < 6; j++){
                uint32_t H[4];
                #pragma unroll
                for (int g = 0; g < 2; g++){
                    int kb = 16 * j + 2 * lm + g * 8;
                    #pragma unroll
                    for (int r = 0; r < 2; r++){
                        float v[2];
                        #pragma unroll
                        for (int e = 0; e < 2; e++){
                            int k = kb + e, c = k >> 5, tt = k & 31;
                            float s, co;
                            sincosf(xa[t][r][c] * ((float)(1 << (tt & 15)) * PI_F), &s, &co);
                            v[e] = (tt < 16) ? s : co;
                        }
                        H[g * 2 + r] = packh(v[0], v[1]);
                    }
                }
                if (j < 3){
                    #pragma unroll
                    for (int q = 0; q < 4; q++) Ereg[t][j][q] = H[q];
                } else {
                    char* eb = smc + OFF_ENC + (uint32_t)((w * 2 + t) * 3 + (j - 3)) * 512u + lane * 16;
                    *(uint4*)eb = *(uint4*)H;   // own-lane region only
                }
            }
        }
    }

    auto ldenc = [&](int t, int ej, uint32_t* E){   // ej in 3..5
        const char* eb = smc + OFF_ENC + (uint32_t)((w * 2 + t) * 3 + (ej - 3)) * 512u + lane * 16;
        *(uint4*)E = *(const uint4*)(eb);
    };
    // hidden epilogue: bias+ReLU+fp16 pack -> lane-private T stash (smem)
    auto chunk_epi_T = [&](float (&acc)[2][4][4], const float* bp, int c){
        #pragma unroll
        for (int t = 0; t < 2; t++)
            #pragma unroll
            for (int p = 0; p < 2; p++){
                int jo = 2 * c + p;
                float2 ba = __ldg((const float2*)(bp + 16 * jo + 2 * lm));
                float2 bb = __ldg((const float2*)(bp + 16 * jo + 8 + 2 * lm));
                const float* a0 = acc[t][2 * p];
                const float* a1 = acc[t][2 * p + 1];
                uint4 v;
                v.x = packh(fmaxf(a0[0] + ba.x, 0.f), fmaxf(a0[1] + ba.y, 0.f));
                v.y = packh(fmaxf(a0[2] + ba.x, 0.f), fmaxf(a0[3] + ba.y, 0.f));
                v.z = packh(fmaxf(a1[0] + bb.x, 0.f), fmaxf(a1[1] + bb.y, 0.f));
                v.w = packh(fmaxf(a1[2] + bb.x, 0.f), fmaxf(a1[3] + bb.y, 0.f));
                *(uint4*)(smc + OFF_T + (uint32_t)((w * 2 + t) * 8 + jo) * 512u + lane * 16) = v;
            }
    };

    // ---- layer 0: enc(96) -> 128 (chunks 0..3); epilogue straight to A regs ----
    #pragma unroll
    for (int c = 0; c < 4; c++){
        chunk_gate(c);
        float acc[2][4][4];
        #pragma unroll
        for (int t = 0; t < 2; t++)
            #pragma unroll
            for (int nb = 0; nb < 4; nb++)
                #pragma unroll
                for (int q = 0; q < 4; q++) acc[t][nb][q] = 0.f;
        const char* rb = smc + OFF_RING + (uint32_t)(c & 1) * C_STRIDE;
        uint4 c0 = *(const uint4*)(rb + lane * 16);
        uint4 c1 = *(const uint4*)(rb + 512 + lane * 16);
        #pragma unroll
        for (int j = 0; j < 6; j++){
            uint4 n0, n1;
            if (j < 5){
                n0 = *(const uint4*)(rb + (uint32_t)(j + 1) * 1024u + lane * 16);
                n1 = *(const uint4*)(rb + (uint32_t)(j + 1) * 1024u + 512 + lane * 16);
            }
            #pragma unroll
            for (int t = 0; t < 2; t++){
                uint32_t E[4]; const uint32_t* Ap;
                if (j < 3) Ap = Ereg[t][j];
                else      { ldenc(t, j, E); Ap = E; }
                mma_f16(acc[t][0], Ap, c0.x, c0.y);
                mma_f16(acc[t][1], Ap, c0.z, c0.w);
                mma_f16(acc[t][2], Ap, c1.x, c1.y);
                mma_f16(acc[t][3], Ap, c1.z, c1.w);
            }
            c0 = n0; c1 = n1;
        }
        // epilogue -> A regs directly (layer 0 only); lane-local, no barrier
        #pragma unroll
        for (int t = 0; t < 2; t++)
            #pragma unroll
            for (int p = 0; p < 2; p++){
                int jo = 2 * c + p;
                float2 ba = __ldg((const float2*)(b0g + 16 * jo + 2 * lm));
                float2 bb = __ldg((const float2*)(b0g + 16 * jo + 8 + 2 * lm));
                const float* a0 = acc[t][2 * p];
                const float* a1 = acc[t][2 * p + 1];
                A[t][jo][0] = packh(fmaxf(a0[0] + ba.x, 0.f), fmaxf(a0[1] + ba.y, 0.f));
                A[t][jo][1] = packh(fmaxf(a0[2] + ba.x, 0.f), fmaxf(a0[3] + ba.y, 0.f));
                A[t][jo][2] = packh(fmaxf(a1[0] + bb.x, 0.f), fmaxf(a1[1] + bb.y, 0.f));
                A[t][jo][3] = packh(fmaxf(a1[2] + bb.x, 0.f), fmaxf(a1[3] + bb.y, 0.f));
            }
    }

    // ---- 7 hidden layers: [H(128)|enc(96)] -> 128 (chunks 4..31) ----
    for (int l = 0; l < 7; l++){
        const float* bp = bhg + l * 128;
        #pragma unroll
        for (int c = 0; c < 4; c++){
            chunk_gate(4 + l * 4 + c);
            float acc[2][4][4];
            #pragma unroll
            for (int t = 0; t < 2; t++)
                #pragma unroll
                for (int nb = 0; nb < 4; nb++)
                    #pragma unroll
                    for (int q = 0; q < 4; q++) acc[t][nb][q] = 0.f;
            const char* rb = smc + OFF_RING + (uint32_t)((4 + l * 4 + c) & 1) * C_STRIDE;
            uint4 c0 = *(const uint4*)(rb + lane * 16);
            uint4 c1 = *(const uint4*)(rb + 512 + lane * 16);
            #pragma unroll
            for (int j = 0; j < 14; j++){
                uint4 n0, n1;
                if (j < 13){
                    n0 = *(const uint4*)(rb + (uint32_t)(j + 1) * 1024u + lane * 16);
                    n1 = *(const uint4*)(rb + (uint32_t)(j + 1) * 1024u + 512 + lane * 16);
                }
                #pragma unroll
                for (int t = 0; t < 2; t++){
                    uint32_t E[4]; const uint32_t* Ap;
                    if (j < 8)       Ap = A[t][j];
                    else if (j < 11) Ap = Ereg[t][j - 8];
                    else            { ldenc(t, j - 8, E); Ap = E; }
                    mma_f16(acc[t][0], Ap, c0.x, c0.y);
                    mma_f16(acc[t][1], Ap, c0.z, c0.w);
                    mma_f16(acc[t][2], Ap, c1.x, c1.y);
                    mma_f16(acc[t][3], Ap, c1.z, c1.w);
                }
                c0 = n0; c1 = n1;
            }
            chunk_epi_T(acc, bp, c);   // lane-private smem; no barrier needed
        }
        // reload A regs from lane-private T stash (same lane wrote it; no sync)
        #pragma unroll
        for (int t = 0; t < 2; t++)
            #pragma unroll
            for (int j = 0; j < 8; j++){
                uint4 v = *(const uint4*)(smc + OFF_T + (uint32_t)((w * 2 + t) * 8 + j) * 512u + lane * 16);
                A[t][j][0] = v.x; A[t][j][1] = v.y; A[t][j][2] = v.z; A[t][j][3] = v.w;
            }
    }

    // ---- final layer: [H|enc](224) -> 4 (N padded to 8), chunk 32 ----
    asm volatile("cp.async.wait_group 0;");
    __syncthreads();
    float fac[2][4];
    #pragma unroll
    for (int t = 0; t < 2; t++)
        #pragma unroll
        for (int q = 0; q < 4; q++) fac[t][q] = 0.f;
    {
        const char* rb = smc + OFF_RING;   // slot 32&1 = 0
        #pragma unroll
        for (int j = 0; j < 14; j++){
            const char* fb = rb + (uint32_t)j * 256u + lane * 8;
            uint64_t bh = *(const uint64_t*)fb;
            #pragma unroll
            for (int t = 0; t < 2; t++){
                uint32_t E[4]; const uint32_t* Ap;
                if (j < 8)       Ap = A[t][j];
                else if (j < 11) Ap = Ereg[t][j - 8];
                else            { ldenc(t, j - 8, E); Ap = E; }
                mma_f16(fac[t], Ap, (uint32_t)bh, (uint32_t)(bh >> 32));
            }
        }
    }
    #pragma unroll
    for (int t = 0; t < 2; t++){
        if (lm < 2){
            int n0 = 2 * lm;
            float bv0 = __ldg(blg + n0), bv1 = __ldg(blg + n0 + 1);
            int p0 = gp0 + w * 32 + t * 16 + l4;
            *(float2*)(out + p0 * 4 + n0)       = make_float2(fac[t][0] + bv0, fac[t][1] + bv1);
            *(float2*)(out + (p0 + 8) * 4 + n0) = make_float2(fac[t][2] + bv0, fac[t][3] + bv1);
        }
    }
}

extern "C" void kernel_launch(void* const* d_in, const int* in_sizes, int n_in,
                              void* d_out, int out_size) {
    const float* qp = (const float*)d_in[0];
    const float* W0 = (const float*)d_in[1];
    const float* b0 = (const float*)d_in[2];
    const float* Wh = (const float*)d_in[3];
    const float* bh = (const float*)d_in[4];
    const float* Wl = (const float*)d_in[5];
    const float* bl = (const float*)d_in[6];
    float* out = (float*)d_out;

    int n = in_sizes[0] / 3;   // 524288
    const int NPREP = 7 * 28672 + 96 * 128 + 224 * 8;
    prep_kernel<<<(NPREP + 255) / 256, 256>>>(W0, Wh, Wl);
    cudaFuncSetAttribute(nf_main, cudaFuncAttributeMaxDynamicSharedMemorySize, (int)SMEM_TOT);
    nf_main<<<n / NPTS, THREADS, SMEM_TOT>>>(qp, b0, bh, bl, out);
}